// round 16
// baseline (speedup 1.0000x reference)
#include <cuda_runtime.h>
#include <cuda_fp16.h>
#include <cstdint>

// Problem constants
#define NN 100000
#define EE 1600000
#define RR 12
#define F_IN 16
#define HID 128
#define OUTD 64
#define PP 4096
#define NK (NN * RR)             // 1,200,000 (dst,etype) segments
#define MT 100096                // NN padded to 64 (1564 * 64)
#define KBIG ((RR + 1) * HID)    // 1664
#define K0 ((RR + 1) * F_IN)     // 208 (layer0 K, no padding)
#define NB1 ((NK + 1023) / 1024) // scan blocks
#define NTILES (MT / 64)         // 1564
#define PGRID 296                // persistent grid (2 CTAs x 148 SMs)

// ---------------- scratch (device globals; no allocation allowed) -------------
__device__ __half g_BT[HID * KBIG];          // B^T [out_col][k] (fp16)
__device__ __half g_HA[(size_t)NN * HID];    // inter-layer activations (fp16)
__device__ __half g_HB[(size_t)NN * HID];
__device__ float  g_Hf32[(size_t)NN * OUTD]; // layer3 output (fp32)
__device__ int    g_deg[NK + 2];
__device__ int    g_off[NK + 2];
__device__ int    g_cur[NK + 2];
__device__ int    g_bsum[NB1 + 2];
__device__ int    g_boff[NB1 + 2];
__device__ unsigned g_csr[EE];               // src only (segments encode dst,etype)
__device__ float  g_hf[NN * 2];
__device__ int    g_ticket[4];               // per-layer work tickets

// ======================= mma.sync helpers (sm_100 baseline ISA) ===============
__device__ __forceinline__ uint32_t smem_u32(const void* p) {
    return (uint32_t)__cvta_generic_to_shared(p);
}
__device__ __forceinline__ void ldm_x4(uint32_t* r, uint32_t addr) {
    asm volatile("ldmatrix.sync.aligned.m8n8.x4.shared.b16 {%0,%1,%2,%3}, [%4];"
        : "=r"(r[0]), "=r"(r[1]), "=r"(r[2]), "=r"(r[3]) : "r"(addr));
}
__device__ __forceinline__ void ldm_x2(uint32_t* r, uint32_t addr) {
    asm volatile("ldmatrix.sync.aligned.m8n8.x2.shared.b16 {%0,%1}, [%2];"
        : "=r"(r[0]), "=r"(r[1]) : "r"(addr));
}
__device__ __forceinline__ void mma_16816(float* d, const uint32_t* a, const uint32_t* b) {
    asm volatile("mma.sync.aligned.m16n8k16.row.col.f32.f16.f16.f32 "
        "{%0,%1,%2,%3}, {%4,%5,%6,%7}, {%8,%9}, {%0,%1,%2,%3};"
        : "+f"(d[0]), "+f"(d[1]), "+f"(d[2]), "+f"(d[3])
        : "r"(a[0]), "r"(a[1]), "r"(a[2]), "r"(a[3]), "r"(b[0]), "r"(b[1]));
}
__device__ __forceinline__ void cp16(uint32_t dst, const void* src) {
    asm volatile("cp.async.cg.shared.global [%0], [%1], 16;" :: "r"(dst), "l"(src));
}
__device__ __forceinline__ void cp_commit() { asm volatile("cp.async.commit_group;"); }
template <int N>
__device__ __forceinline__ void cp_wait() { asm volatile("cp.async.wait_group %0;" :: "n"(N)); }

// round float4 to packed fp16x4
__device__ __forceinline__ uint2 round4h(float4 a) {
    uint2 u;
    *(__half2*)&u.x = __floats2half2_rn(a.x, a.y);
    *(__half2*)&u.y = __floats2half2_rn(a.z, a.w);
    return u;
}

// ---------------- CSR build over (dst*12 + etype) keys ------------------------
__global__ void zeroDegKernel() {
    int i = blockIdx.x * blockDim.x + threadIdx.x;
    if (i <= NK) g_deg[i] = 0;
    if (i < 4) g_ticket[i] = 0;
}
__global__ void histKernel(const int* __restrict__ dst, const int* __restrict__ et) {
    int e = blockIdx.x * blockDim.x + threadIdx.x;
    if (e < EE) atomicAdd(&g_deg[dst[e] * RR + et[e]], 1);
}
__global__ void scanK1() {
    __shared__ int sh[1024];
    int t = threadIdx.x;
    int i = blockIdx.x * 1024 + t;
    int v = (i < NK) ? g_deg[i] : 0;
    sh[t] = v;
    __syncthreads();
    for (int s = 1; s < 1024; s <<= 1) {
        int tmp = (t >= s) ? sh[t - s] : 0;
        __syncthreads();
        sh[t] += tmp;
        __syncthreads();
    }
    if (i < NK) g_off[i] = sh[t];
    if (t == 1023) g_bsum[blockIdx.x] = sh[1023];
}
__global__ void scanK2() {
    __shared__ int sh[1024];
    __shared__ int carry;
    int t = threadIdx.x;
    if (t == 0) carry = 0;
    __syncthreads();
    for (int base = 0; base < NB1; base += 1024) {
        int i = base + t;
        int v = (i < NB1) ? g_bsum[i] : 0;
        sh[t] = v;
        __syncthreads();
        for (int s = 1; s < 1024; s <<= 1) {
            int tmp = (t >= s) ? sh[t - s] : 0;
            __syncthreads();
            sh[t] += tmp;
            __syncthreads();
        }
        if (i < NB1) g_boff[i] = carry + sh[t] - v;
        int tot = sh[1023];
        __syncthreads();
        if (t == 0) carry += tot;
        __syncthreads();
    }
    if (t == 0) g_off[NK] = carry;
}
__global__ void scanK3() {
    int i = blockIdx.x * blockDim.x + threadIdx.x;
    if (i >= NK) return;
    int excl = g_off[i] + g_boff[i >> 10] - g_deg[i];
    g_off[i] = excl;
    g_cur[i] = excl;
}
__global__ void scatterKernel(const int* __restrict__ src, const int* __restrict__ dst,
                              const int* __restrict__ et) {
    int e = blockIdx.x * blockDim.x + threadIdx.x;
    if (e >= EE) return;
    int key = dst[e] * RR + et[e];
    int pos = atomicAdd(&g_cur[key], 1);
    g_csr[pos] = (unsigned)src[e];
}

// ---------------- weights: BT[o][kk] fp16, kk = r*din + i (r==12 -> L) --------
__global__ void buildBTKernel(const float* __restrict__ W, const float* __restrict__ L,
                              int K, int NO, int din) {
    int idx = blockIdx.x * blockDim.x + threadIdx.x;
    if (idx >= NO * K) return;
    int o = idx / K, kk = idx % K;
    int r = kk / din, i = kk % din;
    float w = 0.f;
    if (r < RR)       w = W[((size_t)r * din + i) * NO + o];
    else if (r == RR) w = L[(size_t)i * NO + o];
    g_BT[idx] = __float2half(w);
}

// ---------------- FUSED layer0: gather(h0) + flat HMMA GEMM -------------------
// Ticket-scheduled persistent CTAs. Per tile: full-B cp.async (128x208 fp16),
// gather all 13 K-chunks (16 cols each) into sA, ONE sync, 13 k16 MMA steps.
#define PAD0 232   // fp16 elements per smem row (464 B = 29 x 16B, odd -> ldm ok)
#define SOFF_INTS (64 * RR + 1)               // 769
#define F0_SMEM ((64 + 128) * PAD0 * 2 + SOFF_INTS * 4 + 32)  // 92196

__global__ __launch_bounds__(256, 2) void gemmFused0(
    const float* __restrict__ h0,
    const __half* __restrict__ BT,
    const float* __restrict__ bias, __half* __restrict__ out)
{
    extern __shared__ __half sm[];
    __half* sA = sm;
    __half* sB = sA + 64 * PAD0;
    int* sOff = (int*)(sB + 128 * PAD0);
    int* sTile = sOff + SOFF_INTS;

    int tid = threadIdx.x, wid = tid >> 5, lane = tid & 31;
    int wrow = wid >> 2, wcol = wid & 3;  // 2 m-warps x 4 n-warps, 32x32 each
    int lrow0 = wid * 8;                  // this warp's local gather rows
    int half_ = lane >> 4;                // row-pair selector
    int l = lane & 15;                    // column within din=16

#pragma unroll 1
    for (;;) {
        __syncthreads();
        if (tid == 0) sTile[0] = atomicAdd(&g_ticket[0], 1);
        __syncthreads();
        int tile = sTile[0];
        if (tile >= NTILES) break;
        int row0 = tile * 64;

        // stage CSR offsets for this tile (coalesced)
        {
            size_t base = (size_t)row0 * RR;
            for (int i = tid; i < SOFF_INTS; i += 256)
                sOff[i] = (base + i <= (size_t)NK) ? g_off[base + i] : 0;
        }
        __syncthreads();

        // full B tile via cp.async (L2-resident; 128 rows x 26 x 16B)
        for (int c = tid; c < 128 * 26; c += 256) {
            int row = c / 26, kc = (c % 26) << 3;
            cp16(smem_u32(sB + row * PAD0 + kc), BT + row * K0 + kc);
        }
        cp_commit();

        // gather all 12 relation chunks + self chunk into sA
        // each warp: 8 rows as 4 row-pairs; lane half_ selects row, l = column
#pragma unroll 1
        for (int r = 0; r < RR; r++) {
            int e0[4], d[4];
#pragma unroll
            for (int j = 0; j < 4; j++) {
                int lr = lrow0 + 2 * j + half_;
                int n = row0 + lr;
                if (n < NN) {
                    int o = sOff[lr * RR + r];
                    e0[j] = o;
                    d[j] = sOff[lr * RR + r + 1] - o;
                } else { e0[j] = 0; d[j] = 0; }
            }
            unsigned s0[4], s1[4];
#pragma unroll
            for (int j = 0; j < 4; j++) {
                s0[j] = (d[j] > 0) ? g_csr[e0[j]] : 0u;
                s1[j] = (d[j] > 1) ? g_csr[e0[j] + 1] : 0u;
            }
            float g[4];
#pragma unroll
            for (int j = 0; j < 4; j++) g[j] = 0.f;
#pragma unroll
            for (int j = 0; j < 4; j++)
                if (d[j] > 0) g[j] += __ldg(h0 + (size_t)s0[j] * F_IN + l);
#pragma unroll
            for (int j = 0; j < 4; j++)
                if (d[j] > 1) g[j] += __ldg(h0 + (size_t)s1[j] * F_IN + l);
            // tail (deg > 2)
            int e[4], en[4];
            bool any = false;
#pragma unroll
            for (int j = 0; j < 4; j++) {
                e[j] = e0[j] + 2;
                en[j] = e0[j] + d[j];
                any |= (e[j] < en[j]);
            }
            while (any) {
                any = false;
#pragma unroll
                for (int j = 0; j < 4; j++) {
                    if (e[j] < en[j]) {
                        unsigned s = g_csr[e[j]++];
                        g[j] += __ldg(h0 + (size_t)s * F_IN + l);
                        any |= (e[j] < en[j]);
                    }
                }
            }
#pragma unroll
            for (int j = 0; j < 4; j++) {
                int lr = lrow0 + 2 * j + half_;
                sA[lr * PAD0 + r * F_IN + l] = __float2half(g[j]);
            }
        }
        // self chunk (r == RR)
#pragma unroll
        for (int j = 0; j < 4; j++) {
            int lr = lrow0 + 2 * j + half_;
            int n = row0 + lr;
            float v = (n < NN) ? __ldg(h0 + (size_t)n * F_IN + l) : 0.f;
            sA[lr * PAD0 + RR * F_IN + l] = __float2half(v);
        }

        cp_wait<0>();
        __syncthreads();

        // MMA: 13 k16 steps over K0=208
        float acc[2][4][4];
#pragma unroll
        for (int mi = 0; mi < 2; mi++)
#pragma unroll
            for (int nj = 0; nj < 4; nj++)
#pragma unroll
                for (int j = 0; j < 4; j++) acc[mi][nj][j] = 0.f;
        uint32_t uA = smem_u32(sA);
        uint32_t uB = smem_u32(sB);
        int lrA = lane & 15;
        int lkA = (lane >> 4) << 3;
        int lnB = lane & 7;
        int lkB = ((lane >> 3) & 1) << 3;
#pragma unroll
        for (int ks = 0; ks < RR + 1; ks++) {
            int k0 = ks << 4;
            uint32_t bh[4][2];
#pragma unroll
            for (int nj = 0; nj < 4; nj++) {
                int nb = wcol * 32 + nj * 8 + lnB;
                ldm_x2(bh[nj], uB + (nb * PAD0 + k0 + lkB) * 2);
            }
#pragma unroll
            for (int mi = 0; mi < 2; mi++) {
                int m = wrow * 32 + mi * 16 + lrA;
                uint32_t ah[4];
                ldm_x4(ah, uA + (m * PAD0 + k0 + lkA) * 2);
#pragma unroll
                for (int nj = 0; nj < 4; nj++)
                    mma_16816(acc[mi][nj], ah, bh[nj]);
            }
        }

        // epilogue: bias + relu + fp16 store (NO = 128)
#pragma unroll
        for (int mi = 0; mi < 2; mi++) {
            int gr = row0 + wrow * 32 + mi * 16 + (lane >> 2);
#pragma unroll
            for (int nj = 0; nj < 4; nj++) {
                int gc = wcol * 32 + nj * 8 + (lane & 3) * 2;
                float bx = __ldg(bias + gc), by = __ldg(bias + gc + 1);
                if (gr < NN)
                    *(__half2*)(out + (size_t)gr * HID + gc) =
                        __floats2half2_rn(fmaxf(acc[mi][nj][0] + bx, 0.f),
                                          fmaxf(acc[mi][nj][1] + by, 0.f));
                if (gr + 8 < NN)
                    *(__half2*)(out + (size_t)(gr + 8) * HID + gc) =
                        __floats2half2_rn(fmaxf(acc[mi][nj][2] + bx, 0.f),
                                          fmaxf(acc[mi][nj][3] + by, 0.f));
            }
        }
    }
}

// ---------------- FUSED agg + HMMA GEMM (layers 1-3), ticket-scheduled --------
// R14-proven structure: per chunk r: STS gathered chunk, cp.async B chunk,
// two-phase gather of chunk r+1, MMA chunk r (x2 B-fragment loads).
#define PADE 136   // fp16 elements per smem row (272 B)
#define FUSED_SMEM ((64 + 128) * PADE * 2 + SOFF_INTS * 4 + 32)  // 55360 bytes

template <bool OUTH>
__global__ __launch_bounds__(256, 2) void gemmFused(
    const __half* __restrict__ h,
    const __half* __restrict__ BT,
    int NO, const float* __restrict__ bias, void* __restrict__ outv, int layerIdx)
{
    extern __shared__ __half sm[];
    __half* sA = sm;
    __half* sB = sA + 64 * PADE;
    int* sOff = (int*)(sB + 128 * PADE);
    int* sTile = sOff + SOFF_INTS;

    int tid = threadIdx.x, wid = tid >> 5, lane = tid & 31;
    int wrow = wid >> 2, wcol = wid & 3;  // 2 m-warps x 4 n-warps, 32x32 each
    int lrow0 = wid * 8;                  // this warp's local gather rows

    // zero B tail rows once (cp.async below never touches rows >= NO)
    if (NO < 128) {
        uint32_t* zb = (uint32_t*)(sB + NO * PADE);
        int cnt = (128 - NO) * (PADE / 2);
        for (int i = tid; i < cnt; i += 256) zb[i] = 0u;
    }

    // load 4 fp16 H values for (node s, this lane's 4 cols) -> float4
    auto ld4h = [&](unsigned s) -> float4 {
        uint2 raw = *(const uint2*)(h + (size_t)s * HID + lane * 4);
        __half2 p0 = *(__half2*)&raw.x, p1 = *(__half2*)&raw.y;
        float2 f0 = __half22float2(p0), f1 = __half22float2(p1);
        return make_float4(f0.x, f0.y, f1.x, f1.y);
    };

    int rbase = 0;
    float4 g[8];  // gathered A chunk (8 rows per warp, float4 per lane)

    // two-phase gather of chunk r (offsets from smem; csr then h, batched)
    auto gatherChunk = [&](int r) {
#pragma unroll
        for (int i = 0; i < 8; i++) g[i] = make_float4(0.f, 0.f, 0.f, 0.f);
        if (r == RR) {
#pragma unroll
            for (int i = 0; i < 8; i++) {
                int n = rbase + i;
                if (n < NN) g[i] = ld4h((unsigned)n);
            }
            return;
        }
        int e0[8], d[8];
#pragma unroll
        for (int i = 0; i < 8; i++) {
            int n = rbase + i;
            if (n < NN) {
                int o = sOff[(lrow0 + i) * RR + r];
                e0[i] = o;
                d[i] = sOff[(lrow0 + i) * RR + r + 1] - o;
            } else { e0[i] = 0; d[i] = 0; }
        }
        unsigned s0[8], s1[8];
#pragma unroll
        for (int i = 0; i < 8; i++) {
            s0[i] = (d[i] > 0) ? g_csr[e0[i]] : 0u;
            s1[i] = (d[i] > 1) ? g_csr[e0[i] + 1] : 0u;
        }
#pragma unroll
        for (int i = 0; i < 8; i++) {
            if (d[i] > 0) {
                float4 v = ld4h(s0[i]);
                g[i].x += v.x; g[i].y += v.y; g[i].z += v.z; g[i].w += v.w;
            }
        }
#pragma unroll
        for (int i = 0; i < 8; i++) {
            if (d[i] > 1) {
                float4 v = ld4h(s1[i]);
                g[i].x += v.x; g[i].y += v.y; g[i].z += v.z; g[i].w += v.w;
            }
        }
        int e[8], en[8];
        bool any = false;
#pragma unroll
        for (int i = 0; i < 8; i++) {
            e[i] = e0[i] + 2;
            en[i] = e0[i] + d[i];
            any |= (e[i] < en[i]);
        }
        while (any) {
            any = false;
#pragma unroll
            for (int i = 0; i < 8; i++) {
                if (e[i] < en[i]) {
                    unsigned s = g_csr[e[i]++];
                    float4 v = ld4h(s);
                    g[i].x += v.x; g[i].y += v.y; g[i].z += v.z; g[i].w += v.w;
                    any |= (e[i] < en[i]);
                }
            }
        }
    };

#pragma unroll 1
    for (;;) {
        // grab next tile via ticket (sync also guards prev tile's smem reads)
        __syncthreads();
        if (tid == 0) sTile[0] = atomicAdd(&g_ticket[layerIdx], 1);
        __syncthreads();
        int tile = sTile[0];
        if (tile >= NTILES) break;
        int row0 = tile * 64;
        rbase = row0 + lrow0;

        // stage CSR offsets for this tile (coalesced)
        {
            size_t base = (size_t)row0 * RR;
            for (int i = tid; i < SOFF_INTS; i += 256)
                sOff[i] = (base + i <= (size_t)NK) ? g_off[base + i] : 0;
        }
        __syncthreads();

        float acc[2][4][4];
#pragma unroll
        for (int mi = 0; mi < 2; mi++)
#pragma unroll
            for (int nj = 0; nj < 4; nj++)
#pragma unroll
                for (int j = 0; j < 4; j++) acc[mi][nj][j] = 0.f;

        gatherChunk(0);

#pragma unroll 1
        for (int r = 0; r < RR + 1; r++) {
            __syncthreads();  // previous chunk's MMA done; sA/sB reusable
            // STS: gathered chunk r (rounded to fp16) into sA
#pragma unroll
            for (int i = 0; i < 8; i++) {
                int row = lrow0 + i;
                *(uint2*)(sA + row * PADE + lane * 4) = round4h(g[i]);
            }
            // B chunk r via cp.async (weights L2-resident)
            for (int c = tid; c < NO * 16; c += 256) {
                int row = c >> 4, kc = (c & 15) << 3;
                size_t gg = (size_t)row * KBIG + r * HID + kc;
                cp16(smem_u32(sB + row * PADE + kc), BT + gg);
            }
            cp_commit();
            // gather next chunk while cp.async B is in flight
            if (r < RR) gatherChunk(r + 1);
            cp_wait<0>();
            __syncthreads();
            // MMA: 8 k16 steps over the 128-col chunk (x2 B loads, R14-proven)
            int lrA = lane & 15;
            int lkA = (lane >> 4) << 3;
            int lnB = lane & 7;
            int lkB = ((lane >> 3) & 1) << 3;
#pragma unroll
            for (int ks = 0; ks < 8; ks++) {
                int k0 = ks << 4;
                uint32_t bh[4][2];
#pragma unroll
                for (int nj = 0; nj < 4; nj++) {
                    int nb = wcol * 32 + nj * 8 + lnB;
                    ldm_x2(bh[nj], smem_u32(sB + nb * PADE + k0 + lkB));
                }
#pragma unroll
                for (int mi = 0; mi < 2; mi++) {
                    int m = wrow * 32 + mi * 16 + lrA;
                    uint32_t ah[4];
                    ldm_x4(ah, smem_u32(sA + m * PADE + k0 + lkA));
#pragma unroll
                    for (int nj = 0; nj < 4; nj++)
                        mma_16816(acc[mi][nj], ah, bh[nj]);
                }
            }
        }

        // epilogue: bias + relu + store (fp16 H or fp32 final)
#pragma unroll
        for (int mi = 0; mi < 2; mi++) {
            int gr = row0 + wrow * 32 + mi * 16 + (lane >> 2);
#pragma unroll
            for (int nj = 0; nj < 4; nj++) {
                int gc = wcol * 32 + nj * 8 + (lane & 3) * 2;
                if (gc < NO) {
                    float bx = __ldg(bias + gc), by = __ldg(bias + gc + 1);
                    float v0 = fmaxf(acc[mi][nj][0] + bx, 0.f);
                    float v1 = fmaxf(acc[mi][nj][1] + by, 0.f);
                    float v2 = fmaxf(acc[mi][nj][2] + bx, 0.f);
                    float v3 = fmaxf(acc[mi][nj][3] + by, 0.f);
                    if (OUTH) {
                        __half* out = (__half*)outv;
                        if (gr < NN)
                            *(__half2*)(out + (size_t)gr * NO + gc) = __floats2half2_rn(v0, v1);
                        if (gr + 8 < NN)
                            *(__half2*)(out + (size_t)(gr + 8) * NO + gc) = __floats2half2_rn(v2, v3);
                    } else {
                        float* out = (float*)outv;
                        if (gr < NN)
                            *(float2*)(out + (size_t)gr * NO + gc) = make_float2(v0, v1);
                        if (gr + 8 < NN)
                            *(float2*)(out + (size_t)(gr + 8) * NO + gc) = make_float2(v2, v3);
                    }
                }
            }
        }
    }
}

// ---------------- final dense (64 -> 2) ---------------------------------------
__global__ void finalKernel(const float* __restrict__ Wd, const float* __restrict__ bd) {
    int n = blockIdx.x * blockDim.x + threadIdx.x;
    if (n >= NN) return;
    float a0 = bd[0], a1 = bd[1];
    const float* hr = g_Hf32 + (size_t)n * OUTD;
#pragma unroll 8
    for (int o = 0; o < OUTD; o++) {
        float h = hr[o];
        a0 += h * Wd[o * 2 + 0];
        a1 += h * Wd[o * 2 + 1];
    }
    g_hf[n * 2 + 0] = a0;
    g_hf[n * 2 + 1] = a1;
}

// ---------------- edge scoring output -----------------------------------------
__global__ void outputKernel(const int* __restrict__ ei, float* __restrict__ out) {
    int p = blockIdx.x * blockDim.x + threadIdx.x;
    if (p >= PP) return;
    int u1 = ei[p * 4 + 0], v1 = ei[p * 4 + 1];
    int u2 = ei[p * 4 + 2], v2 = ei[p * 4 + 3];
    out[p * 2 + 0] = 0.5f * (g_hf[u1 * 2 + 0] + g_hf[v1 * 2 + 0]);
    out[p * 2 + 1] = 0.5f * (g_hf[u1 * 2 + 1] + g_hf[v1 * 2 + 1]);
    out[PP * 2 + p * 2 + 0] = 0.5f * (g_hf[u2 * 2 + 0] + g_hf[v2 * 2 + 0]);
    out[PP * 2 + p * 2 + 1] = 0.5f * (g_hf[u2 * 2 + 1] + g_hf[v2 * 2 + 1]);
}

// ---------------- launch ------------------------------------------------------
static inline int cdiv(int a, int b) { return (a + b - 1) / b; }

extern "C" void kernel_launch(void* const* d_in, const int* in_sizes, int n_in,
                              void* d_out, int out_size) {
    const float* h0  = (const float*)d_in[0];
    const int* src   = (const int*)d_in[1];
    const int* dst   = (const int*)d_in[2];
    const int* et    = (const int*)d_in[3];
    const int* ei    = (const int*)d_in[4];
    const float* W[4] = { (const float*)d_in[5],  (const float*)d_in[8],
                          (const float*)d_in[11], (const float*)d_in[14] };
    const float* L[4] = { (const float*)d_in[6],  (const float*)d_in[9],
                          (const float*)d_in[12], (const float*)d_in[15] };
    const float* b[4] = { (const float*)d_in[7],  (const float*)d_in[10],
                          (const float*)d_in[13], (const float*)d_in[16] };
    const float* Wd = (const float*)d_in[17];
    const float* bd = (const float*)d_in[18];
    float* out = (float*)d_out;

    cudaFuncSetAttribute(gemmFused0, cudaFuncAttributeMaxDynamicSharedMemorySize, F0_SMEM);
    cudaFuncSetAttribute(gemmFused<true>, cudaFuncAttributeMaxDynamicSharedMemorySize, FUSED_SMEM);
    cudaFuncSetAttribute(gemmFused<false>, cudaFuncAttributeMaxDynamicSharedMemorySize, FUSED_SMEM);

    __half *pBT, *pHA, *pHB;
    float *pHf;
    cudaGetSymbolAddress((void**)&pBT, g_BT);
    cudaGetSymbolAddress((void**)&pHA, g_HA);
    cudaGetSymbolAddress((void**)&pHB, g_HB);
    cudaGetSymbolAddress((void**)&pHf, g_Hf32);

    // ---- CSR over (dst*12+etype) ----
    zeroDegKernel<<<cdiv(NK + 1, 256), 256>>>();
    histKernel<<<cdiv(EE, 256), 256>>>(dst, et);
    scanK1<<<NB1, 1024>>>();
    scanK2<<<1, 1024>>>();
    scanK3<<<cdiv(NK, 256), 256>>>();
    scatterKernel<<<cdiv(EE, 256), 256>>>(src, dst, et);

    // ---- layer 0: fused gather(h0)+GEMM, K0=208, fp16 H out ----
    buildBTKernel<<<cdiv(HID * K0, 256), 256>>>(W[0], L[0], K0, HID, F_IN);
    gemmFused0<<<PGRID, 256, F0_SMEM>>>(h0, pBT, b[0], pHA);

    // ---- layers 1-3: fused agg+GEMM, persistent CTAs, ticket-scheduled ----
    buildBTKernel<<<cdiv(HID * KBIG, 256), 256>>>(W[1], L[1], KBIG, HID, HID);
    gemmFused<true><<<PGRID, 256, FUSED_SMEM>>>(pHA, pBT, HID, b[1], (void*)pHB, 1);

    buildBTKernel<<<cdiv(HID * KBIG, 256), 256>>>(W[2], L[2], KBIG, HID, HID);
    gemmFused<true><<<PGRID, 256, FUSED_SMEM>>>(pHB, pBT, HID, b[2], (void*)pHA, 2);

    buildBTKernel<<<cdiv(OUTD * KBIG, 256), 256>>>(W[3], L[3], KBIG, OUTD, HID);
    gemmFused<false><<<PGRID, 256, FUSED_SMEM>>>(pHA, pBT, OUTD, b[3], (void*)pHf, 3);

    finalKernel<<<cdiv(NN, 256), 256>>>(Wd, bd);
    outputKernel<<<cdiv(PP, 256), 256>>>(ei, out);
}

// round 17
// speedup vs baseline: 1.0451x; 1.0451x over previous
#include <cuda_runtime.h>
#include <cuda_fp16.h>
#include <cstdint>

// Problem constants
#define NN 100000
#define EE 1600000
#define RR 12
#define F_IN 16
#define HID 128
#define OUTD 64
#define PP 4096
#define NK (NN * RR)             // 1,200,000 (dst,etype) segments
#define MT 100096                // NN padded to 64 (1564 * 64)
#define KBIG ((RR + 1) * HID)    // 1664
#define K0P 256                  // layer0 K padded (13*16=208 -> 256)
#define NB1 ((NK + 1023) / 1024) // scan blocks
#define NTILES (MT / 64)         // 1564
#define PGRID 296                // persistent grid (2 CTAs x 148 SMs)

// ---------------- scratch (device globals; no allocation allowed) -------------
__device__ __half g_A0[(size_t)MT * K0P];    // layer0 GEMM A (fp16)
__device__ __half g_BT[HID * KBIG];          // B^T [out_col][k] (fp16)
__device__ __half g_HA[(size_t)NN * HID];    // inter-layer activations (fp16)
__device__ __half g_HB[(size_t)NN * HID];
__device__ float  g_Hf32[(size_t)NN * OUTD]; // layer3 output (fp32)
__device__ int    g_deg[NK + 2];
__device__ int    g_off[NK + 2];
__device__ int    g_cur[NK + 2];
__device__ int    g_bsum[NB1 + 2];
__device__ int    g_boff[NB1 + 2];
__device__ unsigned g_csr[EE];               // src only (segments encode dst,etype)
__device__ float  g_hf[NN * 2];
__device__ int    g_ticket[4];               // per-fused-layer work tickets

// ======================= mma.sync helpers (sm_100 baseline ISA) ===============
__device__ __forceinline__ uint32_t smem_u32(const void* p) {
    return (uint32_t)__cvta_generic_to_shared(p);
}
__device__ __forceinline__ void ldm_x4(uint32_t* r, uint32_t addr) {
    asm volatile("ldmatrix.sync.aligned.m8n8.x4.shared.b16 {%0,%1,%2,%3}, [%4];"
        : "=r"(r[0]), "=r"(r[1]), "=r"(r[2]), "=r"(r[3]) : "r"(addr));
}
__device__ __forceinline__ void ldm_x2(uint32_t* r, uint32_t addr) {
    asm volatile("ldmatrix.sync.aligned.m8n8.x2.shared.b16 {%0,%1}, [%2];"
        : "=r"(r[0]), "=r"(r[1]) : "r"(addr));
}
__device__ __forceinline__ void mma_16816(float* d, const uint32_t* a, const uint32_t* b) {
    asm volatile("mma.sync.aligned.m16n8k16.row.col.f32.f16.f16.f32 "
        "{%0,%1,%2,%3}, {%4,%5,%6,%7}, {%8,%9}, {%0,%1,%2,%3};"
        : "+f"(d[0]), "+f"(d[1]), "+f"(d[2]), "+f"(d[3])
        : "r"(a[0]), "r"(a[1]), "r"(a[2]), "r"(a[3]), "r"(b[0]), "r"(b[1]));
}
__device__ __forceinline__ void cp16(uint32_t dst, const void* src) {
    asm volatile("cp.async.cg.shared.global [%0], [%1], 16;" :: "r"(dst), "l"(src));
}
__device__ __forceinline__ void cp_commit() { asm volatile("cp.async.commit_group;"); }
template <int N>
__device__ __forceinline__ void cp_wait() { asm volatile("cp.async.wait_group %0;" :: "n"(N)); }

// round float4 to packed fp16x4
__device__ __forceinline__ uint2 round4h(float4 a) {
    uint2 u;
    *(__half2*)&u.x = __floats2half2_rn(a.x, a.y);
    *(__half2*)&u.y = __floats2half2_rn(a.z, a.w);
    return u;
}

// ---------------- CSR build over (dst*12 + etype) keys ------------------------
__global__ void zeroDegKernel() {
    int i = blockIdx.x * blockDim.x + threadIdx.x;
    if (i <= NK) g_deg[i] = 0;
    if (i < 4) g_ticket[i] = 0;
}
__global__ void histKernel(const int* __restrict__ dst, const int* __restrict__ et) {
    int e = blockIdx.x * blockDim.x + threadIdx.x;
    if (e < EE) atomicAdd(&g_deg[dst[e] * RR + et[e]], 1);
}
__global__ void scanK1() {
    __shared__ int sh[1024];
    int t = threadIdx.x;
    int i = blockIdx.x * 1024 + t;
    int v = (i < NK) ? g_deg[i] : 0;
    sh[t] = v;
    __syncthreads();
    for (int s = 1; s < 1024; s <<= 1) {
        int tmp = (t >= s) ? sh[t - s] : 0;
        __syncthreads();
        sh[t] += tmp;
        __syncthreads();
    }
    if (i < NK) g_off[i] = sh[t];
    if (t == 1023) g_bsum[blockIdx.x] = sh[1023];
}
__global__ void scanK2() {
    __shared__ int sh[1024];
    __shared__ int carry;
    int t = threadIdx.x;
    if (t == 0) carry = 0;
    __syncthreads();
    for (int base = 0; base < NB1; base += 1024) {
        int i = base + t;
        int v = (i < NB1) ? g_bsum[i] : 0;
        sh[t] = v;
        __syncthreads();
        for (int s = 1; s < 1024; s <<= 1) {
            int tmp = (t >= s) ? sh[t - s] : 0;
            __syncthreads();
            sh[t] += tmp;
            __syncthreads();
        }
        if (i < NB1) g_boff[i] = carry + sh[t] - v;
        int tot = sh[1023];
        __syncthreads();
        if (t == 0) carry += tot;
        __syncthreads();
    }
    if (t == 0) g_off[NK] = carry;
}
__global__ void scanK3() {
    int i = blockIdx.x * blockDim.x + threadIdx.x;
    if (i >= NK) return;
    int excl = g_off[i] + g_boff[i >> 10] - g_deg[i];
    g_off[i] = excl;
    g_cur[i] = excl;
}
__global__ void scatterKernel(const int* __restrict__ src, const int* __restrict__ dst,
                              const int* __restrict__ et) {
    int e = blockIdx.x * blockDim.x + threadIdx.x;
    if (e >= EE) return;
    int key = dst[e] * RR + et[e];
    int pos = atomicAdd(&g_cur[key], 1);
    g_csr[pos] = (unsigned)src[e];
}

// ---------------- weights: BT[o][kk] fp16, kk = r*din + i (r==12 -> L) --------
__global__ void buildBTKernel(const float* __restrict__ W, const float* __restrict__ L,
                              int K, int NO, int din) {
    int idx = blockIdx.x * blockDim.x + threadIdx.x;
    if (idx >= NO * K) return;
    int o = idx / K, kk = idx % K;
    int r = kk / din, i = kk % din;
    float w = 0.f;
    if (r < RR)       w = W[((size_t)r * din + i) * NO + o];
    else if (r == RR) w = L[(size_t)i * NO + o];
    g_BT[idx] = __float2half(w);
}

// ---------------- aggregation layer0 (din=16): 2 nodes per warp ---------------
__global__ void agg0Kernel(const float* __restrict__ h0) {
    int gw = (blockIdx.x * blockDim.x + threadIdx.x) >> 5;
    int lane = threadIdx.x & 31;
    int n = gw * 2 + (lane >> 4);   // two nodes per warp
    int l = lane & 15;
    if (n >= NN) return;
    size_t ab = (size_t)n * K0P;
#pragma unroll 1
    for (int r = 0; r < RR; r++) {
        int e0 = g_off[n * RR + r], e1 = g_off[n * RR + r + 1];
        float acc = 0.f;
        for (int e = e0; e < e1; e++) {
            unsigned s = g_csr[e];
            acc += __ldg(h0 + (size_t)s * F_IN + l);
        }
        g_A0[ab + r * F_IN + l] = __float2half(acc);
    }
    g_A0[ab + RR * F_IN + l] = __float2half(__ldg(h0 + (size_t)n * F_IN + l));
    if (l < 12) {  // zero pad cols 208..255 (12 lanes x 4 halves)
        *(uint2*)&g_A0[ab + 208 + l * 4] = make_uint2(0u, 0u);
    }
}

// ---------------- layer0 pipelined HMMA GEMM (unfused, K=256, fp16 out) -------
// stage: A 64x144B | B 128x144B = 27648 B; x2 stages
#define STAGE_B 27648
#define GEMM_SMEM (2 * STAGE_B)

__global__ __launch_bounds__(256, 2) void gemmK(
    const __half* __restrict__ A, const __half* __restrict__ BT,
    int K, int NO, const float* __restrict__ bias, __half* __restrict__ out)
{
    extern __shared__ char smem[];
    int tid = threadIdx.x, wid = tid >> 5, lane = tid & 31;
    int row0 = blockIdx.x * 64;
    int wrow = wid & 1, wcol = wid >> 1;

    auto loadStage = [&](int s, int k0) {
        char* st = smem + s * STAGE_B;
        for (int c = tid; c < 512; c += 256) {
            int row = c >> 3, kc = (c & 7) << 3;
            size_t g = (size_t)(row0 + row) * K + k0 + kc;
            cp16(smem_u32(st + row * 144 + kc * 2), A + g);
        }
        for (int c = tid; c < 1024; c += 256) {
            int row = c >> 3, kc = (c & 7) << 3;
            size_t g = (size_t)row * K + k0 + kc;
            cp16(smem_u32(st + 9216 + row * 144 + kc * 2), BT + g);
        }
    };

    float acc[2][4][4];
#pragma unroll
    for (int mi = 0; mi < 2; mi++)
#pragma unroll
        for (int nj = 0; nj < 4; nj++)
#pragma unroll
            for (int j = 0; j < 4; j++) acc[mi][nj][j] = 0.f;

    int KITERS = K >> 6;
    loadStage(0, 0);
    cp_commit();

    for (int kt = 0; kt < KITERS; kt++) {
        if (kt + 1 < KITERS) {
            loadStage((kt + 1) & 1, (kt + 1) << 6);
            cp_commit();
            cp_wait<1>();
        } else {
            cp_wait<0>();
        }
        __syncthreads();
        uint32_t uA = smem_u32(smem + (kt & 1) * STAGE_B);
        uint32_t uB = uA + 9216;
#pragma unroll
        for (int k16 = 0; k16 < 4; k16++) {
            int koA = (k16 << 4) + ((lane >> 4) << 3);
            int rowA = wrow * 32 + (lane & 15);
            uint32_t ah[2][4];
            ldm_x4(ah[0], uA + rowA * 144 + koA * 2);
            ldm_x4(ah[1], uA + (rowA + 16) * 144 + koA * 2);
            int koB = (k16 << 4) + (((lane >> 3) & 1) << 3);
            int rowB = wcol * 32 + ((lane >> 4) << 3) + (lane & 7);
            uint32_t bh[2][4];
            ldm_x4(bh[0], uB + rowB * 144 + koB * 2);
            ldm_x4(bh[1], uB + (rowB + 16) * 144 + koB * 2);
#pragma unroll
            for (int mi = 0; mi < 2; mi++)
#pragma unroll
                for (int nj = 0; nj < 4; nj++) {
                    const uint32_t* bf = &bh[nj >> 1][(nj & 1) * 2];
                    mma_16816(acc[mi][nj], ah[mi], bf);
                }
        }
        __syncthreads();
    }

#pragma unroll
    for (int mi = 0; mi < 2; mi++) {
        int gr = row0 + wrow * 32 + mi * 16 + (lane >> 2);
#pragma unroll
        for (int nj = 0; nj < 4; nj++) {
            int gc = wcol * 32 + nj * 8 + (lane & 3) * 2;
            if (gc < NO) {
                float bx = __ldg(bias + gc), by = __ldg(bias + gc + 1);
                if (gr < NN) {
                    *(__half2*)(out + (size_t)gr * NO + gc) =
                        __floats2half2_rn(fmaxf(acc[mi][nj][0] + bx, 0.f),
                                          fmaxf(acc[mi][nj][1] + by, 0.f));
                }
                if (gr + 8 < NN) {
                    *(__half2*)(out + (size_t)(gr + 8) * NO + gc) =
                        __floats2half2_rn(fmaxf(acc[mi][nj][2] + bx, 0.f),
                                          fmaxf(acc[mi][nj][3] + by, 0.f));
                }
            }
        }
    }
}

// ---------------- FUSED agg + HMMA GEMM (layers 1-3), ticket-scheduled --------
// R14-proven structure. OUTH=true (HID layers): 2x4 warp grid, 128 cols.
// OUTH=false (layer3, NO=64): 4x2 warp grid, 16x32 per warp -> half the MMAs,
// no zero-fill, half the B traffic.
#define PADE 136   // fp16 elements per smem row (272 B)
#define SOFF_INTS (64 * RR + 1)               // 769
#define FUSED_SMEM ((64 + 128) * PADE * 2 + SOFF_INTS * 4 + 32)  // 55360 bytes

template <bool OUTH>
__global__ __launch_bounds__(256, 2) void gemmFused(
    const __half* __restrict__ h,
    const __half* __restrict__ BT,
    int NO, const float* __restrict__ bias, void* __restrict__ outv, int layerIdx)
{
    extern __shared__ __half sm[];
    __half* sA = sm;
    __half* sB = sA + 64 * PADE;
    int* sOff = (int*)(sB + 128 * PADE);
    int* sTile = sOff + SOFF_INTS;

    int tid = threadIdx.x, wid = tid >> 5, lane = tid & 31;
    constexpr int MI = OUTH ? 2 : 1;           // m sub-tiles per warp
    constexpr int WM = OUTH ? 32 : 16;         // rows per warp
    int wrow = OUTH ? (wid >> 2) : (wid >> 1);
    int wcol = OUTH ? (wid & 3) : (wid & 1);
    int lrow0 = wid * 8;                       // this warp's local gather rows

    // load 4 fp16 H values for (node s, this lane's 4 cols) -> float4
    auto ld4h = [&](unsigned s) -> float4 {
        uint2 raw = *(const uint2*)(h + (size_t)s * HID + lane * 4);
        __half2 p0 = *(__half2*)&raw.x, p1 = *(__half2*)&raw.y;
        float2 f0 = __half22float2(p0), f1 = __half22float2(p1);
        return make_float4(f0.x, f0.y, f1.x, f1.y);
    };

    int rbase = 0;
    float4 g[8];  // gathered A chunk (8 rows per warp, float4 per lane)

    // two-phase gather of chunk r (offsets from smem; csr then h, batched)
    auto gatherChunk = [&](int r) {
#pragma unroll
        for (int i = 0; i < 8; i++) g[i] = make_float4(0.f, 0.f, 0.f, 0.f);
        if (r == RR) {
#pragma unroll
            for (int i = 0; i < 8; i++) {
                int n = rbase + i;
                if (n < NN) g[i] = ld4h((unsigned)n);
            }
            return;
        }
        int e0[8], d[8];
#pragma unroll
        for (int i = 0; i < 8; i++) {
            int n = rbase + i;
            if (n < NN) {
                int o = sOff[(lrow0 + i) * RR + r];
                e0[i] = o;
                d[i] = sOff[(lrow0 + i) * RR + r + 1] - o;
            } else { e0[i] = 0; d[i] = 0; }
        }
        unsigned s0[8], s1[8];
#pragma unroll
        for (int i = 0; i < 8; i++) {
            s0[i] = (d[i] > 0) ? g_csr[e0[i]] : 0u;
            s1[i] = (d[i] > 1) ? g_csr[e0[i] + 1] : 0u;
        }
#pragma unroll
        for (int i = 0; i < 8; i++) {
            if (d[i] > 0) {
                float4 v = ld4h(s0[i]);
                g[i].x += v.x; g[i].y += v.y; g[i].z += v.z; g[i].w += v.w;
            }
        }
#pragma unroll
        for (int i = 0; i < 8; i++) {
            if (d[i] > 1) {
                float4 v = ld4h(s1[i]);
                g[i].x += v.x; g[i].y += v.y; g[i].z += v.z; g[i].w += v.w;
            }
        }
        int e[8], en[8];
        bool any = false;
#pragma unroll
        for (int i = 0; i < 8; i++) {
            e[i] = e0[i] + 2;
            en[i] = e0[i] + d[i];
            any |= (e[i] < en[i]);
        }
        while (any) {
            any = false;
#pragma unroll
            for (int i = 0; i < 8; i++) {
                if (e[i] < en[i]) {
                    unsigned s = g_csr[e[i]++];
                    float4 v = ld4h(s);
                    g[i].x += v.x; g[i].y += v.y; g[i].z += v.z; g[i].w += v.w;
                    any |= (e[i] < en[i]);
                }
            }
        }
    };

#pragma unroll 1
    for (;;) {
        // grab next tile via ticket (sync also guards prev tile's smem reads)
        __syncthreads();
        if (tid == 0) sTile[0] = atomicAdd(&g_ticket[layerIdx], 1);
        __syncthreads();
        int tile = sTile[0];
        if (tile >= NTILES) break;
        int row0 = tile * 64;
        rbase = row0 + lrow0;

        // stage CSR offsets for this tile (coalesced)
        {
            size_t base = (size_t)row0 * RR;
            for (int i = tid; i < SOFF_INTS; i += 256)
                sOff[i] = (base + i <= (size_t)NK) ? g_off[base + i] : 0;
        }
        __syncthreads();

        float acc[MI][4][4];
#pragma unroll
        for (int mi = 0; mi < MI; mi++)
#pragma unroll
            for (int nj = 0; nj < 4; nj++)
#pragma unroll
                for (int j = 0; j < 4; j++) acc[mi][nj][j] = 0.f;

        gatherChunk(0);

#pragma unroll 1
        for (int r = 0; r < RR + 1; r++) {
            __syncthreads();  // previous chunk's MMA done; sA/sB reusable
            // STS: gathered chunk r (rounded to fp16) into sA
#pragma unroll
            for (int i = 0; i < 8; i++) {
                int row = lrow0 + i;
                *(uint2*)(sA + row * PADE + lane * 4) = round4h(g[i]);
            }
            // B chunk r via cp.async (weights L2-resident; NO rows only)
            for (int c = tid; c < NO * 16; c += 256) {
                int row = c >> 4, kc = (c & 15) << 3;
                size_t gg = (size_t)row * KBIG + r * HID + kc;
                cp16(smem_u32(sB + row * PADE + kc), BT + gg);
            }
            cp_commit();
            // gather next chunk while cp.async B is in flight
            if (r < RR) gatherChunk(r + 1);
            cp_wait<0>();
            __syncthreads();
            // MMA: 8 k16 steps over the 128-col chunk (x2 B loads, R14-proven)
            int lrA = lane & 15;
            int lkA = (lane >> 4) << 3;
            int lnB = lane & 7;
            int lkB = ((lane >> 3) & 1) << 3;
#pragma unroll
            for (int ks = 0; ks < 8; ks++) {
                int k0 = ks << 4;
                uint32_t bh[4][2];
#pragma unroll
                for (int nj = 0; nj < 4; nj++) {
                    int nb = wcol * 32 + nj * 8 + lnB;
                    ldm_x2(bh[nj], smem_u32(sB + nb * PADE + k0 + lkB));
                }
#pragma unroll
                for (int mi = 0; mi < MI; mi++) {
                    int m = wrow * WM + mi * 16 + lrA;
                    uint32_t ah[4];
                    ldm_x4(ah, smem_u32(sA + m * PADE + k0 + lkA));
#pragma unroll
                    for (int nj = 0; nj < 4; nj++)
                        mma_16816(acc[mi][nj], ah, bh[nj]);
                }
            }
        }

        // epilogue: bias + relu + store (fp16 H or fp32 final)
#pragma unroll
        for (int mi = 0; mi < MI; mi++) {
            int gr = row0 + wrow * WM + mi * 16 + (lane >> 2);
#pragma unroll
            for (int nj = 0; nj < 4; nj++) {
                int gc = wcol * 32 + nj * 8 + (lane & 3) * 2;
                if (gc < NO) {
                    float bx = __ldg(bias + gc), by = __ldg(bias + gc + 1);
                    float v0 = fmaxf(acc[mi][nj][0] + bx, 0.f);
                    float v1 = fmaxf(acc[mi][nj][1] + by, 0.f);
                    float v2 = fmaxf(acc[mi][nj][2] + bx, 0.f);
                    float v3 = fmaxf(acc[mi][nj][3] + by, 0.f);
                    if (OUTH) {
                        __half* out = (__half*)outv;
                        if (gr < NN)
                            *(__half2*)(out + (size_t)gr * NO + gc) = __floats2half2_rn(v0, v1);
                        if (gr + 8 < NN)
                            *(__half2*)(out + (size_t)(gr + 8) * NO + gc) = __floats2half2_rn(v2, v3);
                    } else {
                        float* out = (float*)outv;
                        if (gr < NN)
                            *(float2*)(out + (size_t)gr * NO + gc) = make_float2(v0, v1);
                        if (gr + 8 < NN)
                            *(float2*)(out + (size_t)(gr + 8) * NO + gc) = make_float2(v2, v3);
                    }
                }
            }
        }
    }
}

// ---------------- final dense (64 -> 2) ---------------------------------------
__global__ void finalKernel(const float* __restrict__ Wd, const float* __restrict__ bd) {
    int n = blockIdx.x * blockDim.x + threadIdx.x;
    if (n >= NN) return;
    float a0 = bd[0], a1 = bd[1];
    const float* hr = g_Hf32 + (size_t)n * OUTD;
#pragma unroll 8
    for (int o = 0; o < OUTD; o++) {
        float h = hr[o];
        a0 += h * Wd[o * 2 + 0];
        a1 += h * Wd[o * 2 + 1];
    }
    g_hf[n * 2 + 0] = a0;
    g_hf[n * 2 + 1] = a1;
}

// ---------------- edge scoring output -----------------------------------------
__global__ void outputKernel(const int* __restrict__ ei, float* __restrict__ out) {
    int p = blockIdx.x * blockDim.x + threadIdx.x;
    if (p >= PP) return;
    int u1 = ei[p * 4 + 0], v1 = ei[p * 4 + 1];
    int u2 = ei[p * 4 + 2], v2 = ei[p * 4 + 3];
    out[p * 2 + 0] = 0.5f * (g_hf[u1 * 2 + 0] + g_hf[v1 * 2 + 0]);
    out[p * 2 + 1] = 0.5f * (g_hf[u1 * 2 + 1] + g_hf[v1 * 2 + 1]);
    out[PP * 2 + p * 2 + 0] = 0.5f * (g_hf[u2 * 2 + 0] + g_hf[v2 * 2 + 0]);
    out[PP * 2 + p * 2 + 1] = 0.5f * (g_hf[u2 * 2 + 1] + g_hf[v2 * 2 + 1]);
}

// ---------------- launch ------------------------------------------------------
static inline int cdiv(int a, int b) { return (a + b - 1) / b; }

extern "C" void kernel_launch(void* const* d_in, const int* in_sizes, int n_in,
                              void* d_out, int out_size) {
    const float* h0  = (const float*)d_in[0];
    const int* src   = (const int*)d_in[1];
    const int* dst   = (const int*)d_in[2];
    const int* et    = (const int*)d_in[3];
    const int* ei    = (const int*)d_in[4];
    const float* W[4] = { (const float*)d_in[5],  (const float*)d_in[8],
                          (const float*)d_in[11], (const float*)d_in[14] };
    const float* L[4] = { (const float*)d_in[6],  (const float*)d_in[9],
                          (const float*)d_in[12], (const float*)d_in[15] };
    const float* b[4] = { (const float*)d_in[7],  (const float*)d_in[10],
                          (const float*)d_in[13], (const float*)d_in[16] };
    const float* Wd = (const float*)d_in[17];
    const float* bd = (const float*)d_in[18];
    float* out = (float*)d_out;

    cudaFuncSetAttribute(gemmK, cudaFuncAttributeMaxDynamicSharedMemorySize, GEMM_SMEM);
    cudaFuncSetAttribute(gemmFused<true>, cudaFuncAttributeMaxDynamicSharedMemorySize, FUSED_SMEM);
    cudaFuncSetAttribute(gemmFused<false>, cudaFuncAttributeMaxDynamicSharedMemorySize, FUSED_SMEM);

    __half *pA0, *pBT, *pHA, *pHB;
    float *pHf;
    cudaGetSymbolAddress((void**)&pA0, g_A0);
    cudaGetSymbolAddress((void**)&pBT, g_BT);
    cudaGetSymbolAddress((void**)&pHA, g_HA);
    cudaGetSymbolAddress((void**)&pHB, g_HB);
    cudaGetSymbolAddress((void**)&pHf, g_Hf32);

    // ---- CSR over (dst*12+etype) ----
    zeroDegKernel<<<cdiv(NK + 1, 256), 256>>>();
    histKernel<<<cdiv(EE, 256), 256>>>(dst, et);
    scanK1<<<NB1, 1024>>>();
    scanK2<<<1, 1024>>>();
    scanK3<<<cdiv(NK, 256), 256>>>();
    scatterKernel<<<cdiv(EE, 256), 256>>>(src, dst, et);

    // ---- layer 0: din=16, unfused (K=256), fp16 H out ----
    buildBTKernel<<<cdiv(HID * K0P, 256), 256>>>(W[0], L[0], K0P, HID, F_IN);
    agg0Kernel<<<cdiv(NN, 16), 256>>>(h0);
    gemmK<<<NTILES, 256, GEMM_SMEM>>>(pA0, pBT, K0P, HID, b[0], pHA);

    // ---- layers 1-3: fused agg+GEMM, persistent CTAs, ticket-scheduled ----
    buildBTKernel<<<cdiv(HID * KBIG, 256), 256>>>(W[1], L[1], KBIG, HID, HID);
    gemmFused<true><<<PGRID, 256, FUSED_SMEM>>>(pHA, pBT, HID, b[1], (void*)pHB, 1);

    buildBTKernel<<<cdiv(HID * KBIG, 256), 256>>>(W[2], L[2], KBIG, HID, HID);
    gemmFused<true><<<PGRID, 256, FUSED_SMEM>>>(pHB, pBT, HID, b[2], (void*)pHA, 2);

    buildBTKernel<<<cdiv(OUTD * KBIG, 256), 256>>>(W[3], L[3], KBIG, OUTD, HID);
    gemmFused<false><<<PGRID, 256, FUSED_SMEM>>>(pHA, pBT, OUTD, b[3], (void*)pHf, 3);

    finalKernel<<<cdiv(NN, 256), 256>>>(Wd, bd);
    outputKernel<<<cdiv(PP, 256), 256>>>(ei, out);
}